// round 4
// baseline (speedup 1.0000x reference)
#include <cuda_runtime.h>
#include <cuda_bf16.h>

// BuzzLoss: B=8192 rows, T=1024 cols.
// One WARP per row, 8 rows per 256-thread CTA.
// Phase 1: warp loads its row coalesced (8 LDG.128 per array) and stages into
//          padded smem (pad 4 floats per 32 -> conflict-free transpose reads).
// Phase 2 (after __syncwarp only): each thread reads its 32 CONTIGUOUS
//          elements via 8 LDS.128 pairs, serial local exclusive-prefix scan,
//          one 5-step warp product-scan, one warp reduce, one atomicAdd/row.
// No __syncthreads in the whole kernel; 16 shfls per row vs 128 before.

#define FULL_MASK 0xFFFFFFFFu
#define ROWS 8
// padded row buffer: 1024 * 36/32 = 1152 floats
#define ROWBUF 1152
#define SMEM_FLOATS (2 * ROWS * ROWBUF)

__global__ void buzz_zero_kernel(float* out) {
    out[0] = 0.0f;
}

__global__ __launch_bounds__(256, 3)
void buzz_loss_kernel(const float* __restrict__ conf,
                      const float* __restrict__ acc,
                      float* __restrict__ out,
                      float negInvB) {
    extern __shared__ float smem[];

    const int tid  = threadIdx.x;
    const int lane = tid & 31;
    const int wid  = tid >> 5;
    const int row  = blockIdx.x * ROWS + wid;

    float* s_c = smem + (size_t)wid * ROWBUF;
    float* s_a = smem + (size_t)(ROWS + wid) * ROWBUF;

    const float4* c4 = reinterpret_cast<const float4*>(conf + (size_t)row * 1024);
    const float4* a4 = reinterpret_cast<const float4*>(acc  + (size_t)row * 1024);

    // ---- Phase 1: coalesced load + padded smem store (lane-major) ----
    // element p = j*128 + lane*4 ; padded float index f = j*144 + 4*lane + 4*(lane>>3)
    float4 cv[8], av[8];
    #pragma unroll
    for (int j = 0; j < 8; j++) cv[j] = c4[j * 32 + lane];
    #pragma unroll
    for (int j = 0; j < 8; j++) av[j] = a4[j * 32 + lane];

    const int stoff = 4 * lane + 4 * (lane >> 3);
    #pragma unroll
    for (int j = 0; j < 8; j++) {
        *reinterpret_cast<float4*>(s_c + j * 144 + stoff) = cv[j];
        *reinterpret_cast<float4*>(s_a + j * 144 + stoff) = av[j];
    }
    __syncwarp();

    // ---- Phase 2: contiguous chunk per thread ----
    // element k of thread: p = lane*32 + 4g + e ; padded index = 36*lane + 4g + e
    const int ldbase = 36 * lane;

    float pref = 1.0f;
    float s1 = 0.0f, s2 = 0.0f;
    float lastA = 0.0f;

    #pragma unroll
    for (int g = 0; g < 8; g++) {
        const float4 c = *reinterpret_cast<const float4*>(s_c + ldbase + 4 * g);
        const float4 a = *reinterpret_cast<const float4*>(s_a + ldbase + 4 * g);
        float b;
        b = c.x * pref; s1 = fmaf(b, a.x, s1); s2 += b; pref *= (1.0f - c.x);
        b = c.y * pref; s1 = fmaf(b, a.y, s1); s2 += b; pref *= (1.0f - c.y);
        b = c.z * pref; s1 = fmaf(b, a.z, s1); s2 += b; pref *= (1.0f - c.z);
        b = c.w * pref; s1 = fmaf(b, a.w, s1); s2 += b; pref *= (1.0f - c.w);
        if (g == 7) lastA = a.w;      // lane 31: acc[row, 1023]
    }
    // pref == P_lane (product of this thread's 32 factors)

    // Warp inclusive product-scan -> exclusive prefix E
    float inc = pref;
    #pragma unroll
    for (int d = 1; d < 32; d <<= 1) {
        float v = __shfl_up_sync(FULL_MASK, inc, d);
        if (lane >= d) inc *= v;
    }
    float E = __shfl_up_sync(FULL_MASK, inc, 1);
    if (lane == 0) E = 1.0f;

    s1 *= E;
    s2 *= E;

    // Warp reduce
    #pragma unroll
    for (int d = 16; d >= 1; d >>= 1) {
        s1 += __shfl_down_sync(FULL_MASK, s1, d);
        s2 += __shfl_down_sync(FULL_MASK, s2, d);
    }
    const float accLast = __shfl_sync(FULL_MASK, lastA, 31);

    if (lane == 0) {
        const float score = s1 + (1.0f - s2) * accLast;
        atomicAdd(out, score * negInvB);
    }
}

extern "C" void kernel_launch(void* const* d_in, const int* in_sizes, int n_in,
                              void* d_out, int out_size) {
    const float* conf = (const float*)d_in[0];
    const float* acc  = (const float*)d_in[1];
    float* out = (float*)d_out;

    const int total = in_sizes[0];
    const int T = 1024;
    const int B = total / T;
    const size_t smemBytes = SMEM_FLOATS * sizeof(float);   // 73728 B

    cudaFuncSetAttribute(buzz_loss_kernel,
                         cudaFuncAttributeMaxDynamicSharedMemorySize,
                         (int)smemBytes);

    buzz_zero_kernel<<<1, 1>>>(out);
    buzz_loss_kernel<<<B / ROWS, 256, smemBytes>>>(conf, acc, out,
                                                   -1.0f / (float)B);
}

// round 5
// speedup vs baseline: 1.2600x; 1.2600x over previous
#include <cuda_runtime.h>
#include <cuda_bf16.h>

// BuzzLoss: B=8192 rows, T=1024 cols.
// R1 layout (256 threads per row, thread t owns elements [4t,4t+4), coalesced
// float4 loads) but each CTA loops over 8 rows with software prefetch: row
// i+1's 2 LDG.128 are issued before row i's barrier/scan, hiding the serial
// scan chain under memory latency. One barrier per row (double-buffered warp
// products; second-stage reduce replaced by smem atomics). One global atomic
// per CTA.

#define FULL_MASK 0xFFFFFFFFu
#define ROWS_PER_CTA 8

__global__ void buzz_zero_kernel(float* out) {
    out[0] = 0.0f;
}

__global__ __launch_bounds__(256)
void buzz_loss_kernel(const float* __restrict__ conf,
                      const float* __restrict__ acc,
                      float* __restrict__ out,
                      float negInvB) {
    const int tid  = threadIdx.x;
    const int lane = tid & 31;
    const int wid  = tid >> 5;
    const size_t row0 = (size_t)blockIdx.x * ROWS_PER_CTA;

    __shared__ float s_wp[2][8];       // per-warp products, double-buffered
    __shared__ float s_accLast[2];
    __shared__ float s_total;

    if (tid == 0) s_total = 0.0f;

    const float4* c4 = reinterpret_cast<const float4*>(conf + row0 * 1024);
    const float4* a4 = reinterpret_cast<const float4*>(acc  + row0 * 1024);

    // preload row 0
    float4 c = c4[tid];
    float4 a = a4[tid];

    #pragma unroll
    for (int i = 0; i < ROWS_PER_CTA; i++) {
        const int buf = i & 1;

        // prefetch next row before any sync/compute
        float4 cn, an;
        if (i < ROWS_PER_CTA - 1) {
            cn = c4[(i + 1) * 256 + tid];
            an = a4[(i + 1) * 256 + tid];
        }

        const float q0 = 1.0f - c.x;
        const float q1 = 1.0f - c.y;
        const float q2 = 1.0f - c.z;

        // warp inclusive product-scan of per-thread 4-element products
        float inc = q0 * q1 * q2 * (1.0f - c.w);
        #pragma unroll
        for (int d = 1; d < 32; d <<= 1) {
            float v = __shfl_up_sync(FULL_MASK, inc, d);
            if (lane >= d) inc *= v;
        }
        float excl = __shfl_up_sync(FULL_MASK, inc, 1);
        if (lane == 0) excl = 1.0f;

        if (lane == 31) s_wp[buf][wid] = inc;
        if (tid == 255) s_accLast[buf] = a.w;
        __syncthreads();

        // exclusive product over preceding warps
        float wpref = 1.0f;
        #pragma unroll
        for (int w = 0; w < 7; w++) {
            if (w < wid) wpref *= s_wp[buf][w];
        }
        const float E = wpref * excl;
        const float accLast = s_accLast[buf];

        const float b0 = c.x * E;
        const float b1 = c.y * (E * q0);
        const float b2 = c.z * (E * q0 * q1);
        const float b3 = c.w * (E * q0 * q1 * q2);

        float s1 = fmaf(b0, a.x, fmaf(b1, a.y, fmaf(b2, a.z, b3 * a.w)));
        float s2 = (b0 + b1) + (b2 + b3);

        // fold accLast in per-warp: score = sum s1 - accLast*sum s2 + accLast
        float contrib = fmaf(-accLast, s2, s1);

        #pragma unroll
        for (int d = 16; d >= 1; d >>= 1) {
            contrib += __shfl_down_sync(FULL_MASK, contrib, d);
        }
        if (lane == 0) {
            if (wid == 7) contrib += accLast;   // the "+ accLast" term, once per row
            atomicAdd(&s_total, contrib);
        }

        c = cn;
        a = an;
    }

    __syncthreads();
    if (tid == 0) {
        atomicAdd(out, s_total * negInvB);
    }
}

extern "C" void kernel_launch(void* const* d_in, const int* in_sizes, int n_in,
                              void* d_out, int out_size) {
    const float* conf = (const float*)d_in[0];
    const float* acc  = (const float*)d_in[1];
    float* out = (float*)d_out;

    const int total = in_sizes[0];
    const int T = 1024;
    const int B = total / T;

    buzz_zero_kernel<<<1, 1>>>(out);
    buzz_loss_kernel<<<B / ROWS_PER_CTA, 256>>>(conf, acc, out,
                                                -1.0f / (float)B);
}